// round 1
// baseline (speedup 1.0000x reference)
#include <cuda_runtime.h>

#define B_ 256
#define S_ 197
#define D_ 768
#define D4_ 192
#define P_ 20
#define L_ 5
#define T_ 10
#define K_ 5
#define ROWS_TOK 75            // (T+K)*L
#define ROWS_PE 272            // ROWS_TOK + S

// float offsets into d_out
#define PE_OFF   0ULL
#define SIM_OFF  53477376ULL
#define TOK_OFF  53477377ULL
#define IDX_OFF  68222977ULL
#define XN_OFF   68224257ULL

// scratch (device globals; no allocations)
__device__ float g_part[4 * B_ * D_];
__device__ float g_xnorm[B_ * D_];
__device__ float g_pnorm[P_ * D_];
__device__ int   g_idx[B_ * K_];
__device__ int   g_cnt[P_];

// ---------------------------------------------------------------------------
// Kernel 1: stream x_embed -> prompted_embedding[:, 75:, :] and 4-way partial
// sums over S for the mean. grid (B, 4), block 192 (float4 lanes over D).
// ---------------------------------------------------------------------------
__global__ void k_mean_copy(const float4* __restrict__ x, float* __restrict__ out) {
    int b = blockIdx.x;
    int q = blockIdx.y;
    int t = threadIdx.x;                 // 0..191
    int s0 = q * 50;
    int s1 = (q == 3) ? S_ : s0 + 50;

    const float4* xb = x + (size_t)b * S_ * D4_;
    float4* ob = ((float4*)(out + PE_OFF)) + (size_t)b * ROWS_PE * D4_ + (size_t)ROWS_TOK * D4_;

    float4 acc = make_float4(0.f, 0.f, 0.f, 0.f);
    for (int s = s0; s < s1; s++) {
        float4 v = xb[(size_t)s * D4_ + t];
        acc.x += v.x; acc.y += v.y; acc.z += v.z; acc.w += v.w;
        ob[(size_t)s * D4_ + t] = v;
    }
    ((float4*)g_part)[(size_t)q * B_ * D4_ + (size_t)b * D4_ + t] = acc;
}

// 192-thread block reduce (padded to 256 in shared)
__device__ __forceinline__ float blk_reduce_192(float v) {
    __shared__ float sh[256];
    int t = threadIdx.x;
    sh[t] = v;
    if (t < 64) sh[192 + t] = 0.f;
    __syncthreads();
    for (int s = 128; s > 0; s >>= 1) {
        if (t < s) sh[t] += sh[t + s];
        __syncthreads();
    }
    return sh[0];
}

// ---------------------------------------------------------------------------
// Kernel 2: p_norm = l2_normalize(prompt_key). grid P_, block 192.
// ---------------------------------------------------------------------------
__global__ void k_pnorm(const float4* __restrict__ pk) {
    int p = blockIdx.x;
    int t = threadIdx.x;
    float4 v = pk[(size_t)p * D4_ + t];
    float ss = blk_reduce_192(v.x * v.x + v.y * v.y + v.z * v.z + v.w * v.w);
    float r = rsqrtf(fmaxf(ss, 1e-12f));
    float4 n = make_float4(v.x * r, v.y * r, v.z * r, v.w * r);
    ((float4*)g_pnorm)[(size_t)p * D4_ + t] = n;
}

// ---------------------------------------------------------------------------
// Kernel 3: combine partials, mean, l2-normalize; write x_norm to out + scratch.
// grid B_, block 192. Also zeroes g_cnt (block 0).
// ---------------------------------------------------------------------------
__global__ void k_xnorm(float* __restrict__ out) {
    int b = blockIdx.x;
    int t = threadIdx.x;
    const float4* part = (const float4*)g_part;
    float4 a = part[(size_t)0 * B_ * D4_ + (size_t)b * D4_ + t];
    float4 c1 = part[(size_t)1 * B_ * D4_ + (size_t)b * D4_ + t];
    float4 c2 = part[(size_t)2 * B_ * D4_ + (size_t)b * D4_ + t];
    float4 c3 = part[(size_t)3 * B_ * D4_ + (size_t)b * D4_ + t];
    const float inv = 1.0f / (float)S_;
    a.x = (a.x + c1.x + c2.x + c3.x) * inv;
    a.y = (a.y + c1.y + c2.y + c3.y) * inv;
    a.z = (a.z + c1.z + c2.z + c3.z) * inv;
    a.w = (a.w + c1.w + c2.w + c3.w) * inv;
    float ss = blk_reduce_192(a.x * a.x + a.y * a.y + a.z * a.z + a.w * a.w);
    float r = rsqrtf(fmaxf(ss, 1e-12f));
    float4 n = make_float4(a.x * r, a.y * r, a.z * r, a.w * r);
    ((float4*)g_xnorm)[(size_t)b * D4_ + t] = n;
    // x_norm output region starts at odd float offset -> scalar stores
    float* xo = out + XN_OFF + (size_t)b * D_ + (size_t)t * 4;
    xo[0] = n.x; xo[1] = n.y; xo[2] = n.z; xo[3] = n.w;
    if (b == 0 && t < P_) g_cnt[t] = 0;
}

// ---------------------------------------------------------------------------
// Kernel 4: similarity row (20 dots), stable top-5, idx_pruned, counts.
// grid B_, block 32 (one warp).
// ---------------------------------------------------------------------------
__global__ void k_topk(float* __restrict__ out) {
    int b = blockIdx.x;
    int lane = threadIdx.x;
    float acc[P_];
#pragma unroll
    for (int p = 0; p < P_; p++) acc[p] = 0.f;

    const float* xr = g_xnorm + (size_t)b * D_;
    for (int d = lane; d < D_; d += 32) {
        float x = xr[d];
#pragma unroll
        for (int p = 0; p < P_; p++) acc[p] += x * g_pnorm[(size_t)p * D_ + d];
    }
#pragma unroll
    for (int p = 0; p < P_; p++) {
#pragma unroll
        for (int off = 16; off > 0; off >>= 1)
            acc[p] += __shfl_down_sync(0xffffffffu, acc[p], off);
    }
    if (lane == 0) {
        bool used[P_];
#pragma unroll
        for (int p = 0; p < P_; p++) used[p] = false;
        for (int k = 0; k < K_; k++) {
            float best = -3.4e38f;
            int bi = 0;
            for (int p = 0; p < P_; p++) {
                if (!used[p] && acc[p] > best) { best = acc[p]; bi = p; }
            }
            used[bi] = true;
            bool keep = best > 0.0f;
            int idxp = keep ? bi : -1;
            g_idx[b * K_ + k] = idxp;
            out[IDX_OFF + (size_t)b * K_ + k] = (float)idxp;
            if (keep) atomicAdd(&g_cnt[bi], 1);
        }
    }
}

// ---------------------------------------------------------------------------
// Kernel 5: reduce_sim = dot(sum_b x_norm, sum_p cnt[p]*p_norm[p]) / B.
// 1 block, 768 threads.
// ---------------------------------------------------------------------------
__global__ void k_reducesim(float* __restrict__ out) {
    __shared__ float sh[1024];
    int d = threadIdx.x; // 0..767
    float sx = 0.f;
    for (int b = 0; b < B_; b++) sx += g_xnorm[(size_t)b * D_ + d];
    float kt = 0.f;
#pragma unroll
    for (int p = 0; p < P_; p++) kt += (float)g_cnt[p] * g_pnorm[(size_t)p * D_ + d];
    sh[d] = sx * kt;
    if (d < 256) sh[768 + d] = 0.f;
    __syncthreads();
    for (int s = 512; s > 0; s >>= 1) {
        if (d < s) sh[d] += sh[d + s];
        __syncthreads();
    }
    if (d == 0) out[SIM_OFF] = sh[0] * (1.0f / (float)B_);
}

// ---------------------------------------------------------------------------
// Kernel 6: token rows -> prompted_embedding[:, :75, :] AND tokens output.
// grid (75, B_), block 192. PE region is 16B-aligned (float4 stores); tokens
// region starts at odd float offset -> scalar stores.
// ---------------------------------------------------------------------------
__global__ void k_tokens(const float4* __restrict__ prompt,
                         const float4* __restrict__ assist,
                         float* __restrict__ out) {
    int r = blockIdx.x;      // 0..74
    int b = blockIdx.y;
    int t = threadIdx.x;     // 0..191

    float4 v;
    if (r < T_ * L_) {
        v = assist[(size_t)r * D4_ + t];
    } else {
        int rr = r - T_ * L_;
        int k = rr / L_;
        int l = rr % L_;
        int idx = g_idx[b * K_ + k];
        if (idx >= 0)
            v = prompt[((size_t)idx * L_ + l) * D4_ + t];
        else
            v = make_float4(0.f, 0.f, 0.f, 0.f);
    }
    ((float4*)(out + PE_OFF))[(size_t)b * ROWS_PE * D4_ + (size_t)r * D4_ + t] = v;
    float* to = out + TOK_OFF + (size_t)b * ROWS_TOK * D_ + (size_t)r * D_ + (size_t)t * 4;
    to[0] = v.x; to[1] = v.y; to[2] = v.z; to[3] = v.w;
}

extern "C" void kernel_launch(void* const* d_in, const int* in_sizes, int n_in,
                              void* d_out, int out_size) {
    const float4* x_embed = (const float4*)d_in[0];        // [B,S,D]
    const float4* prompt = (const float4*)d_in[1];         // [P,L,D]
    const float4* prompt_key = (const float4*)d_in[2];     // [P,D]
    const float4* assist = (const float4*)d_in[3];         // [T,L,D]
    float* out = (float*)d_out;

    k_mean_copy<<<dim3(B_, 4), D4_>>>(x_embed, out);
    k_pnorm<<<P_, D4_>>>(prompt_key);
    k_xnorm<<<B_, D4_>>>(out);
    k_topk<<<B_, 32>>>(out);
    k_reducesim<<<1, D_>>>(out);
    k_tokens<<<dim3(ROWS_TOK, B_), D4_>>>(prompt, assist, out);
}

// round 2
// speedup vs baseline: 1.2135x; 1.2135x over previous
#include <cuda_runtime.h>

#define B_ 256
#define S_ 197
#define D_ 768
#define D4_ 192
#define P_ 20
#define L_ 5
#define T_ 10
#define K_ 5
#define ROWS_TOK 75            // (T+K)*L
#define ROWS_PE 272            // ROWS_TOK + S

// float offsets into d_out
#define PE_OFF   0ULL
#define SIM_OFF  53477376ULL
#define TOK_OFF  53477377ULL
#define IDX_OFF  68222977ULL
#define XN_OFF   68224257ULL

// scratch (device globals; no allocations)
__device__ float g_part[4 * B_ * D_];
__device__ float g_xnorm[B_ * D_];
__device__ float g_pnorm[P_ * D_];
__device__ int   g_idx[B_ * K_];
__device__ int   g_cnt[P_];

// ---------------------------------------------------------------------------
// Kernel 1: stream x_embed -> prompted_embedding[:, 75:, :] and 4-way partial
// sums over S for the mean. grid (B, 4), block 192 (float4 lanes over D).
// ---------------------------------------------------------------------------
__global__ void k_mean_copy(const float4* __restrict__ x, float* __restrict__ out) {
    int b = blockIdx.x;
    int q = blockIdx.y;
    int t = threadIdx.x;                 // 0..191
    int s0 = q * 50;
    int s1 = (q == 3) ? S_ : s0 + 50;

    const float4* xb = x + (size_t)b * S_ * D4_;
    float4* ob = ((float4*)(out + PE_OFF)) + (size_t)b * ROWS_PE * D4_ + (size_t)ROWS_TOK * D4_;

    float4 acc = make_float4(0.f, 0.f, 0.f, 0.f);
    for (int s = s0; s < s1; s++) {
        float4 v = xb[(size_t)s * D4_ + t];
        acc.x += v.x; acc.y += v.y; acc.z += v.z; acc.w += v.w;
        ob[(size_t)s * D4_ + t] = v;
    }
    ((float4*)g_part)[(size_t)q * B_ * D4_ + (size_t)b * D4_ + t] = acc;
}

// 192-thread block reduce (padded to 256 in shared)
__device__ __forceinline__ float blk_reduce_192(float v) {
    __shared__ float sh[256];
    int t = threadIdx.x;
    sh[t] = v;
    if (t < 64) sh[192 + t] = 0.f;
    __syncthreads();
    for (int s = 128; s > 0; s >>= 1) {
        if (t < s) sh[t] += sh[t + s];
        __syncthreads();
    }
    return sh[0];
}

// ---------------------------------------------------------------------------
// Kernel 2: p_norm = l2_normalize(prompt_key). grid P_, block 192.
// ---------------------------------------------------------------------------
__global__ void k_pnorm(const float4* __restrict__ pk) {
    int p = blockIdx.x;
    int t = threadIdx.x;
    float4 v = pk[(size_t)p * D4_ + t];
    float ss = blk_reduce_192(v.x * v.x + v.y * v.y + v.z * v.z + v.w * v.w);
    float r = rsqrtf(fmaxf(ss, 1e-12f));
    float4 n = make_float4(v.x * r, v.y * r, v.z * r, v.w * r);
    ((float4*)g_pnorm)[(size_t)p * D4_ + t] = n;
}

// ---------------------------------------------------------------------------
// Kernel 3: combine partials, mean, l2-normalize; write x_norm to out + scratch.
// grid B_, block 192. Also zeroes g_cnt (block 0).
// ---------------------------------------------------------------------------
__global__ void k_xnorm(float* __restrict__ out) {
    int b = blockIdx.x;
    int t = threadIdx.x;
    const float4* part = (const float4*)g_part;
    float4 a = part[(size_t)0 * B_ * D4_ + (size_t)b * D4_ + t];
    float4 c1 = part[(size_t)1 * B_ * D4_ + (size_t)b * D4_ + t];
    float4 c2 = part[(size_t)2 * B_ * D4_ + (size_t)b * D4_ + t];
    float4 c3 = part[(size_t)3 * B_ * D4_ + (size_t)b * D4_ + t];
    const float inv = 1.0f / (float)S_;
    a.x = (a.x + c1.x + c2.x + c3.x) * inv;
    a.y = (a.y + c1.y + c2.y + c3.y) * inv;
    a.z = (a.z + c1.z + c2.z + c3.z) * inv;
    a.w = (a.w + c1.w + c2.w + c3.w) * inv;
    float ss = blk_reduce_192(a.x * a.x + a.y * a.y + a.z * a.z + a.w * a.w);
    float r = rsqrtf(fmaxf(ss, 1e-12f));
    float4 n = make_float4(a.x * r, a.y * r, a.z * r, a.w * r);
    ((float4*)g_xnorm)[(size_t)b * D4_ + t] = n;
    // x_norm output region starts at odd float offset -> scalar stores
    float* xo = out + XN_OFF + (size_t)b * D_ + (size_t)t * 4;
    xo[0] = n.x; xo[1] = n.y; xo[2] = n.z; xo[3] = n.w;
    if (b == 0 && t < P_) g_cnt[t] = 0;
}

// ---------------------------------------------------------------------------
// Kernel 4: similarity row (20 dots, one warp per p), top-5, idx_pruned, counts.
// grid B_, block 640 (20 warps). x row staged in shared; p_norm row per warp
// read as float4 (6 per lane).
// ---------------------------------------------------------------------------
__global__ void k_topk(float* __restrict__ out) {
    __shared__ float4 shx[D4_];
    __shared__ float  shsim[P_];
    int b = blockIdx.x;
    int tid = threadIdx.x;               // 0..639
    int w = tid >> 5;                    // warp = prompt index 0..19
    int lane = tid & 31;

    // stage x_norm[b] into shared (192 float4 by first 192 threads)
    if (tid < D4_) shx[tid] = ((const float4*)g_xnorm)[(size_t)b * D4_ + tid];
    __syncthreads();

    // warp w: dot(x, p_norm[w]); 6 float4 per lane
    const float4* pn = ((const float4*)g_pnorm) + (size_t)w * D4_;
    float acc = 0.f;
#pragma unroll
    for (int i = 0; i < 6; i++) {
        int j = lane + 32 * i;
        float4 pv = pn[j];
        float4 xv = shx[j];
        acc += xv.x * pv.x + xv.y * pv.y + xv.z * pv.z + xv.w * pv.w;
    }
#pragma unroll
    for (int off = 16; off > 0; off >>= 1)
        acc += __shfl_down_sync(0xffffffffu, acc, off);
    if (lane == 0) shsim[w] = acc;
    __syncthreads();

    if (tid == 0) {
        float sim[P_];
        bool used[P_];
#pragma unroll
        for (int p = 0; p < P_; p++) { sim[p] = shsim[p]; used[p] = false; }
        for (int k = 0; k < K_; k++) {
            float best = -3.4e38f;
            int bi = 0;
#pragma unroll
            for (int p = 0; p < P_; p++) {
                if (!used[p] && sim[p] > best) { best = sim[p]; bi = p; }
            }
            used[bi] = true;
            bool keep = best > 0.0f;
            int idxp = keep ? bi : -1;
            g_idx[b * K_ + k] = idxp;
            out[IDX_OFF + (size_t)b * K_ + k] = (float)idxp;
            if (keep) atomicAdd(&g_cnt[bi], 1);
        }
    }
}

// ---------------------------------------------------------------------------
// Kernel 5: reduce_sim = dot(sum_b x_norm, sum_p cnt[p]*p_norm[p]) / B.
// 1 block, 768 threads.
// ---------------------------------------------------------------------------
__global__ void k_reducesim(float* __restrict__ out) {
    __shared__ float sh[1024];
    int d = threadIdx.x; // 0..767
    float sx = 0.f;
    for (int b = 0; b < B_; b++) sx += g_xnorm[(size_t)b * D_ + d];
    float kt = 0.f;
#pragma unroll
    for (int p = 0; p < P_; p++) kt += (float)g_cnt[p] * g_pnorm[(size_t)p * D_ + d];
    sh[d] = sx * kt;
    if (d < 256) sh[768 + d] = 0.f;
    __syncthreads();
    for (int s = 512; s > 0; s >>= 1) {
        if (d < s) sh[d] += sh[d + s];
        __syncthreads();
    }
    if (d == 0) out[SIM_OFF] = sh[0] * (1.0f / (float)B_);
}

// ---------------------------------------------------------------------------
// Kernel 6: token rows -> prompted_embedding[:, :75, :] AND tokens output.
// grid (75, B_), block 192. PE region is 16B-aligned (float4 stores); tokens
// region starts at odd float offset -> scalar stores.
// ---------------------------------------------------------------------------
__global__ void k_tokens(const float4* __restrict__ prompt,
                         const float4* __restrict__ assist,
                         float* __restrict__ out) {
    int r = blockIdx.x;      // 0..74
    int b = blockIdx.y;
    int t = threadIdx.x;     // 0..191

    float4 v;
    if (r < T_ * L_) {
        v = assist[(size_t)r * D4_ + t];
    } else {
        int rr = r - T_ * L_;
        int k = rr / L_;
        int l = rr % L_;
        int idx = g_idx[b * K_ + k];
        if (idx >= 0)
            v = prompt[((size_t)idx * L_ + l) * D4_ + t];
        else
            v = make_float4(0.f, 0.f, 0.f, 0.f);
    }
    ((float4*)(out + PE_OFF))[(size_t)b * ROWS_PE * D4_ + (size_t)r * D4_ + t] = v;
    float* to = out + TOK_OFF + (size_t)b * ROWS_TOK * D_ + (size_t)r * D_ + (size_t)t * 4;
    to[0] = v.x; to[1] = v.y; to[2] = v.z; to[3] = v.w;
}

extern "C" void kernel_launch(void* const* d_in, const int* in_sizes, int n_in,
                              void* d_out, int out_size) {
    const float4* x_embed = (const float4*)d_in[0];        // [B,S,D]
    const float4* prompt = (const float4*)d_in[1];         // [P,L,D]
    const float4* prompt_key = (const float4*)d_in[2];     // [P,D]
    const float4* assist = (const float4*)d_in[3];         // [T,L,D]
    float* out = (float*)d_out;

    k_mean_copy<<<dim3(B_, 4), D4_>>>(x_embed, out);
    k_pnorm<<<P_, D4_>>>(prompt_key);
    k_xnorm<<<B_, D4_>>>(out);
    k_topk<<<B_, 640>>>(out);
    k_reducesim<<<1, D_>>>(out);
    k_tokens<<<dim3(ROWS_TOK, B_), D4_>>>(prompt, assist, out);
}